// round 1
// baseline (speedup 1.0000x reference)
#include <cuda_runtime.h>
#include <cuda_bf16.h>

#define N_NODES 50000
#define N_EDGES 800000
#define IN_F    128
#define HD      64      // NUM_HEADS * OUT_FEATS
#define NHEADS  4
#define DOUT    16
#define NEG_SLOPE 0.2f

// ---------------- scratch (no allocs allowed) ----------------
__device__ float4 g_ft[N_NODES * (HD / 4)];   // [N,64] as float4  (12.8 MB)
__device__ float4 g_el[N_NODES];              // [N,4]
__device__ float4 g_er[N_NODES];              // [N,4]
__device__ float4 g_w [N_EDGES];              // exp(e) per edge, [E,4] (12.8 MB)
__device__ float4 g_den[N_NODES];             // softmax denominators [N,4]

__device__ __forceinline__ void red_add_f32x4(float4* addr, float4 v) {
    asm volatile("red.global.add.v4.f32 [%0], {%1,%2,%3,%4};"
                 :: "l"(addr), "f"(v.x), "f"(v.y), "f"(v.z), "f"(v.w)
                 : "memory");
}

__device__ __forceinline__ float lrelu(float x) {
    return x > 0.f ? x : NEG_SLOPE * x;
}

// ---------------- kernel 0: zero out + denom ----------------
__global__ void k_zero(float4* __restrict__ out4) {
    int i = blockIdx.x * blockDim.x + threadIdx.x;
    const float4 z = make_float4(0.f, 0.f, 0.f, 0.f);
    if (i < N_NODES * (HD / 4)) out4[i] = z;      // 800k float4
    if (i < N_NODES)            g_den[i] = z;     // 50k float4
}

// ---------------- kernel 1: ft = feat @ W ; el, er ----------------
// 128 threads/block, 1 node per thread, W resident in smem.
__global__ __launch_bounds__(128) void k_gemm(const float* __restrict__ feat,
                                              const float* __restrict__ W,
                                              const float* __restrict__ attn_l,
                                              const float* __restrict__ attn_r) {
    __shared__ float Ws[IN_F][HD];     // 32 KB, row stride 256B (16B aligned)
    __shared__ float fs[128][17];      // padded: conflict-free per-thread row reads
    __shared__ float al[HD], ar[HD];

    const int t = threadIdx.x;
    // load W (coalesced float4)
    {
        const float4* W4  = (const float4*)W;
        float4*       Ws4 = (float4*)&Ws[0][0];
        #pragma unroll
        for (int i = 0; i < (IN_F * HD / 4) / 128; i++)
            Ws4[i * 128 + t] = W4[i * 128 + t];
    }
    if (t < HD) { al[t] = attn_l[t]; ar[t] = attn_r[t]; }

    const int node = blockIdx.x * 128 + t;

    float4 acc[16];
    #pragma unroll
    for (int j = 0; j < 16; j++) acc[j] = make_float4(0.f, 0.f, 0.f, 0.f);

    for (int kc = 0; kc < IN_F; kc += 16) {
        __syncthreads();
        // load feat tile: 128 nodes x 16 k-values (512 float4, 4 per thread)
        #pragma unroll
        for (int i = 0; i < 4; i++) {
            int lin = i * 128 + t;        // float4 index within tile
            int nn  = lin >> 2;           // node within tile
            int kk  = (lin & 3) * 4;      // k offset within chunk
            int gn  = blockIdx.x * 128 + nn;
            float4 v = make_float4(0.f, 0.f, 0.f, 0.f);
            if (gn < N_NODES)
                v = *(const float4*)(feat + (size_t)gn * IN_F + kc + kk);
            fs[nn][kk + 0] = v.x; fs[nn][kk + 1] = v.y;
            fs[nn][kk + 2] = v.z; fs[nn][kk + 3] = v.w;
        }
        __syncthreads();
        #pragma unroll
        for (int k = 0; k < 16; k++) {
            float fv = fs[t][k];
            const float4* wr = (const float4*)&Ws[kc + k][0];   // broadcast LDS.128
            #pragma unroll
            for (int j = 0; j < 16; j++) {
                float4 w = wr[j];
                acc[j].x += fv * w.x; acc[j].y += fv * w.y;
                acc[j].z += fv * w.z; acc[j].w += fv * w.w;
            }
        }
    }

    if (node < N_NODES) {
        const float* a = (const float*)acc;
        float4 elv, erv;
        float* elp = (float*)&elv;
        float* erp = (float*)&erv;
        #pragma unroll
        for (int h = 0; h < NHEADS; h++) {
            float sl = 0.f, sr = 0.f;
            #pragma unroll
            for (int d = 0; d < DOUT; d++) {
                float v = a[h * DOUT + d];
                sl += v * al[h * DOUT + d];
                sr += v * ar[h * DOUT + d];
            }
            elp[h] = sl; erp[h] = sr;
        }
        g_el[node] = elv;
        g_er[node] = erv;
        float4* fo = &g_ft[node * 16];
        #pragma unroll
        for (int j = 0; j < 16; j++) fo[j] = acc[j];
    }
}

// ---------------- kernel 2: per-edge exp weights + denom ----------------
__global__ void k_edge(const int* __restrict__ src, const int* __restrict__ dst,
                       const float* __restrict__ ew) {
    int e = blockIdx.x * blockDim.x + threadIdx.x;
    if (e >= N_EDGES) return;
    int s = src[e], d = dst[e];
    float4 a = g_el[s];
    float4 b = g_er[d];
    float w = ew[e];
    float4 r;
    r.x = __expf(w * lrelu(a.x + b.x));
    r.y = __expf(w * lrelu(a.y + b.y));
    r.z = __expf(w * lrelu(a.z + b.z));
    r.w = __expf(w * lrelu(a.w + b.w));
    g_w[e] = r;
    red_add_f32x4(&g_den[d], r);
}

// ---------------- kernel 3: normalized weighted scatter ----------------
// 16 threads per edge; each thread handles one float4 (one quarter of one head).
__global__ void k_scatter(const int* __restrict__ src, const int* __restrict__ dst,
                          float4* __restrict__ out4) {
    int gt = blockIdx.x * blockDim.x + threadIdx.x;   // up to 12.8M
    int e = gt >> 4;
    if (e >= N_EDGES) return;
    int q = gt & 15;          // 0..15 -> h = q>>2, 4B4 chunks per head
    int s = __ldg(src + e);
    int d = __ldg(dst + e);
    int h = q >> 2;
    float w  = __ldg((const float*)g_w   + 4 * e + h);
    float dn = __ldg((const float*)g_den + 4 * d + h);
    float a = w / dn;
    float4 f = g_ft[s * 16 + q];
    f.x *= a; f.y *= a; f.z *= a; f.w *= a;
    red_add_f32x4(out4 + (size_t)d * 16 + q, f);
}

// ---------------- launch ----------------
extern "C" void kernel_launch(void* const* d_in, const int* in_sizes, int n_in,
                              void* d_out, int out_size) {
    const float* feat   = (const float*)d_in[0];
    const int*   src    = (const int*)  d_in[1];
    const int*   dst    = (const int*)  d_in[2];
    const float* ew     = (const float*)d_in[3];
    const float* W      = (const float*)d_in[4];
    const float* attn_l = (const float*)d_in[5];
    const float* attn_r = (const float*)d_in[6];
    float4* out4 = (float4*)d_out;

    (void)in_sizes; (void)n_in; (void)out_size;

    {   // zero output + denominators
        int n = N_NODES * (HD / 4);
        k_zero<<<(n + 255) / 256, 256>>>(out4);
    }
    k_gemm<<<(N_NODES + 127) / 128, 128>>>(feat, W, attn_l, attn_r);
    k_edge<<<(N_EDGES + 255) / 256, 256>>>(src, dst, ew);
    {
        long long total = (long long)N_EDGES * 16;
        k_scatter<<<(int)((total + 255) / 256), 256>>>(src, dst, out4);
    }
}